// round 16
// baseline (speedup 1.0000x reference)
#include <cuda_runtime.h>
#include <math.h>
#include <stdint.h>

#define S 4096
#define E 768
#define Hh 12
#define D 64
#define Wb 256
#define TT 513          // band width 2W+1
#define TQA 64          // attn: query rows per CTA (512 threads)
#define TQQ 64          // quasi: query rows per CTA
#define TQP 64          // pv: query rows per CTA
#define NKB 9           // 64-wide key blocks for 32-row tiles
#define NKBQ 10         // 64-wide key blocks for 64-row tiles
#define NEGV -1000000000.0f
#define SCALE 0.125f    // 1/sqrt(64)

// ---------------- scratch (static __device__, no allocations) ----------------
__device__ float g_q [S*E];
__device__ float g_k [S*E];
__device__ float g_v [S*E];
__device__ float g_cq[S*E];
__device__ float g_ck[S*E];
__device__ float g_lam[S*Hh];

__device__ __forceinline__ uint32_t f2tf32(float f) {
    uint32_t u;
    asm("cvt.rna.tf32.f32 %0, %1;" : "=r"(u) : "f"(f));
    return u;
}

#define MMA_TF32(acc, a0,a1,a2,a3, b0,b1)                                    \
    asm("mma.sync.aligned.m16n8k8.row.col.f32.tf32.tf32.f32 "                \
        "{%0,%1,%2,%3}, {%4,%5,%6,%7}, {%8,%9}, {%0,%1,%2,%3};"              \
        : "+f"(acc[0]), "+f"(acc[1]), "+f"(acc[2]), "+f"(acc[3])             \
        : "r"(a0), "r"(a1), "r"(a2), "r"(a3), "r"(b0), "r"(b1))

// ---------------- projection GEMM (tf32 mma.sync, 128x128 CTA tile, R13 winner) ----------------
#define GBM 128
#define GBN 128
#define GBK 32
#define ASTR 136
#define BSTR 136

__global__ __launch_bounds__(256) void gemm5_tc(
    const float* __restrict__ hs, const float* __restrict__ ce,
    const float* __restrict__ Wq,  const float* __restrict__ bq,
    const float* __restrict__ Wk,  const float* __restrict__ bk,
    const float* __restrict__ Wv,  const float* __restrict__ bv,
    const float* __restrict__ Wcq, const float* __restrict__ bcq,
    const float* __restrict__ Wck, const float* __restrict__ bck)
{
    const int which = blockIdx.z;
    const float* A;
    const float* Wt;
    const float* bias;
    float scale = 1.0f;
    float* C;
    switch (which) {
        case 0: A = hs; Wt = Wq;  bias = bq;  C = g_q;  break;
        case 1: A = hs; Wt = Wk;  bias = bk;  C = g_k;  break;
        case 2: A = hs; Wt = Wv;  bias = bv;  C = g_v;  break;
        case 3: A = ce; Wt = Wcq; bias = bcq; C = g_cq; scale = SCALE; break;
        default:A = ce; Wt = Wck; bias = bck; C = g_ck; break;
    }

    __shared__ uint32_t sA[GBK][ASTR];
    __shared__ uint32_t sB[GBK][BSTR];

    const int tid  = threadIdx.x;
    const int warp = tid >> 5;
    const int lane = tid & 31;
    const int wm   = warp & 3;
    const int wn   = warp >> 2;
    const int g    = lane >> 2;
    const int t4   = lane & 3;
    const int m0   = blockIdx.y * GBM;
    const int n0   = blockIdx.x * GBN;

    const int am = tid & 127;
    const int ak = (tid >> 7) * 16;
    const int bk2 = tid >> 3;
    const int bn2 = (tid & 7) * 4;

    const float* Abase = A  + (size_t)(m0 + am) * E + ak;
    const float* Bbase = Wt + (size_t)bk2 * E + n0 + bn2;

    float acc[2][8][4];
    #pragma unroll
    for (int mt = 0; mt < 2; mt++)
        #pragma unroll
        for (int nt = 0; nt < 8; nt++)
            #pragma unroll
            for (int x = 0; x < 4; x++) acc[mt][nt][x] = 0.f;

    for (int k0 = 0; k0 < E; k0 += GBK) {
        #pragma unroll
        for (int i = 0; i < 4; i++) {
            float4 v = *(const float4*)(Abase + k0 + i * 4);
            sA[ak + i*4 + 0][am] = f2tf32(v.x);
            sA[ak + i*4 + 1][am] = f2tf32(v.y);
            sA[ak + i*4 + 2][am] = f2tf32(v.z);
            sA[ak + i*4 + 3][am] = f2tf32(v.w);
        }
        #pragma unroll
        for (int j = 0; j < 4; j++) {
            float4 v = *(const float4*)(Bbase + (size_t)k0 * E + j * 32);
            uint4 u;
            u.x = f2tf32(v.x); u.y = f2tf32(v.y);
            u.z = f2tf32(v.z); u.w = f2tf32(v.w);
            *(uint4*)&sB[bk2][bn2 + j * 32] = u;
        }
        __syncthreads();

        #pragma unroll
        for (int ks = 0; ks < 4; ks++) {
            const int kk = ks * 8;
            uint32_t af[2][4];
            #pragma unroll
            for (int mt = 0; mt < 2; mt++) {
                int mb = wm * 32 + mt * 16 + g;
                af[mt][0] = sA[kk + t4    ][mb];
                af[mt][1] = sA[kk + t4    ][mb + 8];
                af[mt][2] = sA[kk + t4 + 4][mb];
                af[mt][3] = sA[kk + t4 + 4][mb + 8];
            }
            uint32_t bf[8][2];
            #pragma unroll
            for (int nt = 0; nt < 8; nt++) {
                int nb = wn * 64 + nt * 8 + g;
                bf[nt][0] = sB[kk + t4    ][nb];
                bf[nt][1] = sB[kk + t4 + 4][nb];
            }
            #pragma unroll
            for (int mt = 0; mt < 2; mt++)
                #pragma unroll
                for (int nt = 0; nt < 8; nt++)
                    MMA_TF32(acc[mt][nt],
                             af[mt][0], af[mt][1], af[mt][2], af[mt][3],
                             bf[nt][0], bf[nt][1]);
        }
        __syncthreads();
    }

    #pragma unroll
    for (int nt = 0; nt < 8; nt++) {
        int col = n0 + wn * 64 + nt * 8 + 2 * t4;
        float b0v = bias[col], b1v = bias[col + 1];
        #pragma unroll
        for (int mt = 0; mt < 2; mt++) {
            int row = m0 + wm * 32 + mt * 16 + g;
            float2 o;
            o.x = (acc[mt][nt][0] + b0v) * scale;
            o.y = (acc[mt][nt][1] + b1v) * scale;
            *(float2*)&C[(size_t)row * E + col] = o;
            o.x = (acc[mt][nt][2] + b0v) * scale;
            o.y = (acc[mt][nt][3] + b1v) * scale;
            *(float2*)&C[(size_t)(row + 8) * E + col] = o;
        }
    }
}

// ---------------- lam ----------------
__global__ __launch_bounds__(256) void lam_kernel(
    const float* __restrict__ Wlqc, const float* __restrict__ blqc,
    const float* __restrict__ Wlqq, const float* __restrict__ blqq,
    const float* __restrict__ Wlkc, const float* __restrict__ blkc,
    const float* __restrict__ Wlkk, const float* __restrict__ blkk)
{
    int gw   = (blockIdx.x * blockDim.x + threadIdx.x) >> 5;
    int lane = threadIdx.x & 31;
    if (gw >= S * Hh) return;
    int s = gw / Hh, h = gw % Hh;
    size_t base = (size_t)s * E + h * D;

    float a = g_cq[base + lane] * Wlqc[lane] + g_cq[base + lane + 32] * Wlqc[lane + 32]
            + g_q [base + lane] * Wlqq[lane] + g_q [base + lane + 32] * Wlqq[lane + 32];
    float b = g_ck[base + lane] * Wlkc[lane] + g_ck[base + lane + 32] * Wlkc[lane + 32]
            + g_k [base + lane] * Wlkk[lane] + g_k [base + lane + 32] * Wlkk[lane + 32];
    #pragma unroll
    for (int o = 16; o; o >>= 1) {
        a += __shfl_xor_sync(0xffffffffu, a, o);
        b += __shfl_xor_sync(0xffffffffu, b, o);
    }
    if (lane == 0) {
        float lq = 1.f / (1.f + __expf(-(a + blqc[0] + blqq[0])));
        float lk = 1.f / (1.f + __expf(-(b + blkc[0] + blkk[0])));
        g_lam[gw] = 1.f - lq - lk;
    }
}

// ---------------- quasi kernel (TQ=64 streaming, transposed smem, R15 winner) ----------------
#define KSTR 64

__global__ __launch_bounds__(256) void quasi_kernel(
    const int* __restrict__ amask, float* __restrict__ npout)
{
    __shared__ float sCQT[64 * TQQ];   // [d][r] cq rows
    __shared__ float sCKT[64 * KSTR];  // [d][c] cq key block
    __shared__ float sFm[64];

    const int h   = blockIdx.y;
    const int q0  = blockIdx.x * TQQ;
    const int tid = threadIdx.x;
    const int rg  = tid >> 4;          // 0..15 -> rows 4rg..4rg+3
    const int cg  = tid & 15;
    const int r0  = rg << 2;
    const int c0  = cg << 2;

    {
        int lr = tid >> 2;             // 0..63
        int d0 = (tid & 3) << 4;       // 0,16,32,48
        const float4* cqp = (const float4*)(g_cq + (size_t)(q0 + lr) * E + h * D + d0);
        #pragma unroll
        for (int u4 = 0; u4 < 4; u4++) {
            float4 cv = cqp[u4];
            int dd = d0 + u4 * 4;
            sCQT[(dd+0)*TQQ + lr] = cv.x; sCQT[(dd+1)*TQQ + lr] = cv.y;
            sCQT[(dd+2)*TQQ + lr] = cv.z; sCQT[(dd+3)*TQQ + lr] = cv.w;
        }
    }

    float lam[4];
    float* nprow[4];
    #pragma unroll
    for (int i = 0; i < 4; i++) {
        lam[i] = g_lam[(q0 + r0 + i) * Hh + h];
        nprow[i] = npout + ((size_t)(q0 + r0 + i) * Hh + h) * TT;
    }

    const int lc  = tid >> 2;          // 0..63
    const int ld0 = (tid & 3) << 4;    // 0,16,32,48

    for (int b = 0; b < NKBQ; b++) {
        const int kb0 = q0 - Wb + b * 64;
        __syncthreads();
        {
            int j = kb0 + lc;
            bool ok = (j >= 0) && (j < S);
            const float4* cp = (const float4*)(g_cq + (size_t)(ok ? j : 0) * E + h * D + ld0);
            #pragma unroll
            for (int u4 = 0; u4 < 4; u4++) {
                float4 cv = ok ? cp[u4] : make_float4(0.f,0.f,0.f,0.f);
                int dd = ld0 + u4 * 4;
                sCKT[(dd+0)*KSTR + lc] = cv.x; sCKT[(dd+1)*KSTR + lc] = cv.y;
                sCKT[(dd+2)*KSTR + lc] = cv.z; sCKT[(dd+3)*KSTR + lc] = cv.w;
            }
            if (tid < 64) {
                int jj = kb0 + tid;
                sFm[tid] = (jj >= 0 && jj < S && amask[jj] != 0) ? -10000.f : 0.f;
            }
        }
        __syncthreads();

        float acq[4][4];
        #pragma unroll
        for (int i = 0; i < 4; i++)
            #pragma unroll
            for (int jx = 0; jx < 4; jx++) acq[i][jx] = 0.f;

        #pragma unroll 8
        for (int kk = 0; kk < 64; kk++) {
            float4 qv = *(const float4*)&sCQT[kk*TQQ + r0];
            float4 kv = *(const float4*)&sCKT[kk*KSTR + c0];
            acq[0][0] += qv.x*kv.x; acq[0][1] += qv.x*kv.y; acq[0][2] += qv.x*kv.z; acq[0][3] += qv.x*kv.w;
            acq[1][0] += qv.y*kv.x; acq[1][1] += qv.y*kv.y; acq[1][2] += qv.y*kv.z; acq[1][3] += qv.y*kv.w;
            acq[2][0] += qv.z*kv.x; acq[2][1] += qv.z*kv.y; acq[2][2] += qv.z*kv.z; acq[2][3] += qv.z*kv.w;
            acq[3][0] += qv.w*kv.x; acq[3][1] += qv.w*kv.y; acq[3][2] += qv.w*kv.z; acq[3][3] += qv.w*kv.w;
        }

        #pragma unroll
        for (int jx = 0; jx < 4; jx++) {
            int c = c0 + jx;
            int j = kb0 + c;
            bool okj = (j >= 0) && (j < S);
            float fm = sFm[c];
            #pragma unroll
            for (int i = 0; i < 4; i++) {
                int t = b * 64 + c - (r0 + i);
                if (t >= 0 && t <= 512) {
                    float v = okj ? lam[i] / (1.f + __expf(-(acq[i][jx] + fm))) : 0.f;
                    nprow[i][t] = v;
                }
            }
        }
    }
}

// ---------------- attn kernel: TQA=64, 512 threads, 2 rows x 4 cols per thread ----------------
// sQT [d][r] 64x64, sKT [d][c] 64x64 (transposed layouts, R7-verified conflict-free inner loop).
__global__ __launch_bounds__(512, 1) void attn_kernel(
    const int* __restrict__ amask, float* __restrict__ npout)
{
    __shared__ float sQT[64 * TQA];    // [d][r] q rows (pre-scaled)
    __shared__ float sKT[64 * KSTR];   // [d][c] k key block
    __shared__ float sFm[64];

    const int h   = blockIdx.y;
    const int q0  = blockIdx.x * TQA;
    const int tid = threadIdx.x;
    const int rg  = tid >> 4;          // 0..31 -> rows 2rg, 2rg+1
    const int cg  = tid & 15;
    const int r0  = rg << 1;
    const int c0  = cg << 2;

    // fill sQT transposed: lr = row (0..63), 8 floats each
    {
        int lr = tid >> 3;             // 0..63
        int d0 = (tid & 7) << 3;       // 0..56
        const float4* qp = (const float4*)(g_q + (size_t)(q0 + lr) * E + h * D + d0);
        float4 q1 = qp[0], q2 = qp[1];
        sQT[(d0+0)*TQA + lr] = q1.x * SCALE; sQT[(d0+1)*TQA + lr] = q1.y * SCALE;
        sQT[(d0+2)*TQA + lr] = q1.z * SCALE; sQT[(d0+3)*TQA + lr] = q1.w * SCALE;
        sQT[(d0+4)*TQA + lr] = q2.x * SCALE; sQT[(d0+5)*TQA + lr] = q2.y * SCALE;
        sQT[(d0+6)*TQA + lr] = q2.z * SCALE; sQT[(d0+7)*TQA + lr] = q2.w * SCALE;
    }

    float aA[2][NKBQ*4];   // band: 2 rows x 40 (scores, then exp)

    const int lc  = tid >> 3;          // 0..63 key column
    const int ld0 = (tid & 7) << 3;    // 0..56

    #pragma unroll
    for (int b = 0; b < NKBQ; b++) {
        const int kb0 = q0 - Wb + b * 64;
        __syncthreads();
        {
            int j = kb0 + lc;
            bool ok = (j >= 0) && (j < S);
            const float4* kp = (const float4*)(g_k + (size_t)(ok ? j : 0) * E + h * D + ld0);
            float4 k1 = ok ? kp[0] : make_float4(0.f,0.f,0.f,0.f);
            float4 k2 = ok ? kp[1] : make_float4(0.f,0.f,0.f,0.f);
            sKT[(ld0+0)*KSTR + lc] = k1.x; sKT[(ld0+1)*KSTR + lc] = k1.y;
            sKT[(ld0+2)*KSTR + lc] = k1.z; sKT[(ld0+3)*KSTR + lc] = k1.w;
            sKT[(ld0+4)*KSTR + lc] = k2.x; sKT[(ld0+5)*KSTR + lc] = k2.y;
            sKT[(ld0+6)*KSTR + lc] = k2.z; sKT[(ld0+7)*KSTR + lc] = k2.w;
            if (tid < 64) {
                int jj = kb0 + tid;
                sFm[tid] = (jj >= 0 && jj < S && amask[jj] != 0) ? -10000.f : 0.f;
            }
        }
        __syncthreads();

        float acc[2][4] = {{0.f,0.f,0.f,0.f},{0.f,0.f,0.f,0.f}};
        #pragma unroll 8
        for (int kk = 0; kk < 64; kk++) {
            float2 qv = *(const float2*)&sQT[kk*TQA + r0];
            float4 kv = *(const float4*)&sKT[kk*KSTR + c0];
            acc[0][0] += qv.x*kv.x; acc[0][1] += qv.x*kv.y;
            acc[0][2] += qv.x*kv.z; acc[0][3] += qv.x*kv.w;
            acc[1][0] += qv.y*kv.x; acc[1][1] += qv.y*kv.y;
            acc[1][2] += qv.y*kv.z; acc[1][3] += qv.y*kv.w;
        }

        #pragma unroll
        for (int i = 0; i < 2; i++) {
            int r = r0 + i;
            #pragma unroll
            for (int jx = 0; jx < 4; jx++) {
                int c = c0 + jx;
                int t = b * 64 + c - r;
                int j = kb0 + c;
                bool valid = (t >= 0) && (t <= 512) && (j >= 0) && (j < S);
                aA[i][b*4+jx] = valid ? (acc[i][jx] + sFm[c]) : NEGV;
            }
        }
    }

    #pragma unroll
    for (int i = 0; i < 2; i++) {
        int r  = r0 + i;
        int ig = q0 + r;
        float m = NEGV;
        #pragma unroll
        for (int x = 0; x < NKBQ*4; x++) m = fmaxf(m, aA[i][x]);
        #pragma unroll
        for (int o = 8; o; o >>= 1) m = fmaxf(m, __shfl_xor_sync(0xffffffffu, m, o));
        float ssum = 0.f;
        #pragma unroll
        for (int x = 0; x < NKBQ*4; x++) {
            float e = __expf(aA[i][x] - m);
            aA[i][x] = e;
            ssum += e;
        }
        #pragma unroll
        for (int o = 8; o; o >>= 1) ssum += __shfl_xor_sync(0xffffffffu, ssum, o);
        float inv = 1.f / ssum;
        bool  qm  = (amask[ig] != 0);
        float* nprow = npout + ((size_t)ig * Hh + h) * TT;
        #pragma unroll
        for (int b = 0; b < NKBQ; b++) {
            #pragma unroll
            for (int jx = 0; jx < 4; jx++) {
                int t = b * 64 + c0 + jx - r;
                if (t >= 0 && t <= 512) {
                    float np = aA[i][b*4+jx] * inv + nprow[t];
                    nprow[t] = qm ? 0.f : np;
                }
            }
        }
    }
}

// ---------------- PV (SIMT, R7/R13 winner): out = band_pv(new_probs, v) ----------------
#define PSTR 68
#define VSTR 68

__global__ __launch_bounds__(256) void pv_kernel(
    float* __restrict__ outp, const float* __restrict__ npout)
{
    __shared__ float sP[TQP * PSTR];   // [64][68]
    __shared__ float sV[64 * VSTR];    // [64][68]

    const int h   = blockIdx.y;
    const int q0  = blockIdx.x * TQP;
    const int tid = threadIdx.x;
    const int rg  = tid >> 4;          // rows 4rg..4rg+3
    const int dg  = tid & 15;          // d = 4dg..4dg+3

    float acc[4][4];
    #pragma unroll
    for (int i = 0; i < 4; i++)
        #pragma unroll
        for (int j = 0; j < 4; j++) acc[i][j] = 0.f;

    for (int b = 0; b < NKB; b++) {
        int kb0 = q0 - Wb + b * 64;
        __syncthreads();
        {
            int lr  = tid >> 2;
            int c0l = (tid & 3) << 4;
            const float* nprow = npout + ((size_t)(q0 + lr) * Hh + h) * TT;
            #pragma unroll
            for (int x4 = 0; x4 < 4; x4++) {
                int t0 = b * 64 + c0l + x4 * 4 - lr;
                float4 pv4;
                pv4.x = (t0+0 >= 0 && t0+0 <= 512) ? nprow[t0+0] : 0.f;
                pv4.y = (t0+1 >= 0 && t0+1 <= 512) ? nprow[t0+1] : 0.f;
                pv4.z = (t0+2 >= 0 && t0+2 <= 512) ? nprow[t0+2] : 0.f;
                pv4.w = (t0+3 >= 0 && t0+3 <= 512) ? nprow[t0+3] : 0.f;
                *(float4*)&sP[lr * PSTR + c0l + x4 * 4] = pv4;
            }
        }
        {
            int c   = tid >> 2;
            int d0l = (tid & 3) << 4;
            int j = kb0 + c;
            bool ok = (j >= 0) && (j < S);
            const float4* vp = (const float4*)(g_v + (size_t)(ok ? j : 0) * E + h * D + d0l);
            #pragma unroll
            for (int u4 = 0; u4 < 4; u4++) {
                float4 x = ok ? vp[u4] : make_float4(0.f,0.f,0.f,0.f);
                *(float4*)&sV[c * VSTR + d0l + u4 * 4] = x;
            }
        }
        __syncthreads();

        #pragma unroll 4
        for (int c = 0; c < 64; c++) {
            float4 vv = *(const float4*)&sV[c * VSTR + 4 * dg];
            float p0 = sP[(4*rg+0) * PSTR + c];
            float p1 = sP[(4*rg+1) * PSTR + c];
            float p2 = sP[(4*rg+2) * PSTR + c];
            float p3 = sP[(4*rg+3) * PSTR + c];
            acc[0][0] += p0*vv.x; acc[0][1] += p0*vv.y; acc[0][2] += p0*vv.z; acc[0][3] += p0*vv.w;
            acc[1][0] += p1*vv.x; acc[1][1] += p1*vv.y; acc[1][2] += p1*vv.z; acc[1][3] += p1*vv.w;
            acc[2][0] += p2*vv.x; acc[2][1] += p2*vv.y; acc[2][2] += p2*vv.z; acc[2][3] += p2*vv.w;
            acc[3][0] += p3*vv.x; acc[3][1] += p3*vv.y; acc[3][2] += p3*vv.z; acc[3][3] += p3*vv.w;
        }
    }

    #pragma unroll
    for (int i = 0; i < 4; i++) {
        float4 o;
        o.x = acc[i][0]; o.y = acc[i][1]; o.z = acc[i][2]; o.w = acc[i][3];
        *(float4*)(outp + (size_t)(q0 + 4*rg + i) * E + h * D + 4 * dg) = o;
    }
}

// ---------------- launch ----------------
extern "C" void kernel_launch(void* const* d_in, const int* in_sizes, int n_in,
                              void* d_out, int out_size)
{
    (void)in_sizes; (void)n_in; (void)out_size;

    const float* hs    = (const float*)d_in[0];
    const float* ce    = (const float*)d_in[1];
    const int*   amask = (const int*)  d_in[2];
    // d_in[3] is is_index_masked == (attention_mask != 0); derived from amask.
    const float* Wq   = (const float*)d_in[4];
    const float* bq   = (const float*)d_in[5];
    const float* Wk   = (const float*)d_in[6];
    const float* bk   = (const float*)d_in[7];
    const float* Wv   = (const float*)d_in[8];
    const float* bv   = (const float*)d_in[9];
    const float* Wcq  = (const float*)d_in[10];
    const float* bcq  = (const float*)d_in[11];
    const float* Wck  = (const float*)d_in[12];
    const float* bck  = (const float*)d_in[13];
    const float* Wlqc = (const float*)d_in[14];
    const float* blqc = (const float*)d_in[15];
    const float* Wlqq = (const float*)d_in[16];
    const float* blqq = (const float*)d_in[17];
    const float* Wlkc = (const float*)d_in[18];
    const float* blkc = (const float*)d_in[19];
    const float* Wlkk = (const float*)d_in[20];
    const float* blkk = (const float*)d_in[21];

    float* outp  = (float*)d_out;
    float* npout = outp + (size_t)S * E;   // tuple output: [out | new_probs]

    dim3 gg(E / GBN, S / GBM, 5);
    gemm5_tc<<<gg, 256>>>(hs, ce, Wq, bq, Wk, bk, Wv, bv, Wcq, bcq, Wck, bck);

    lam_kernel<<<(S * Hh) / 8, 256>>>(Wlqc, blqc, Wlqq, blqq, Wlkc, blkc, Wlkk, blkk);

    quasi_kernel<<<dim3(S / TQQ, Hh), 256>>>(amask, npout);

    attn_kernel<<<dim3(S / TQA, Hh), 512>>>(amask, npout);

    pv_kernel<<<dim3(S / TQP, Hh), 256>>>(outp, npout);
}

// round 17
// speedup vs baseline: 1.0883x; 1.0883x over previous
#include <cuda_runtime.h>
#include <math.h>
#include <stdint.h>

#define S 4096
#define E 768
#define Hh 12
#define D 64
#define Wb 256
#define TT 513          // band width 2W+1
#define TQ 32           // attn: query rows per CTA
#define TQQ 64          // quasi: query rows per CTA
#define TQP 64          // pv: query rows per CTA
#define NKB 9           // 64-wide key blocks for 32-row tiles
#define NKBQ 10         // 64-wide key blocks for 64-row tiles
#define NEGV -1000000000.0f
#define SCALE 0.125f    // 1/sqrt(64)

// ---------------- scratch (static __device__, no allocations) ----------------
__device__ float g_q [S*E];
__device__ float g_k [S*E];
__device__ float g_v [S*E];
__device__ float g_cq[S*E];
__device__ float g_ck[S*E];
__device__ float g_lam[S*Hh];
__device__ float g_rsum[S*Hh];

__device__ __forceinline__ uint32_t f2tf32(float f) {
    uint32_t u;
    asm("cvt.rna.tf32.f32 %0, %1;" : "=r"(u) : "f"(f));
    return u;
}

#define MMA_TF32(acc, a0,a1,a2,a3, b0,b1)                                    \
    asm("mma.sync.aligned.m16n8k8.row.col.f32.tf32.tf32.f32 "                \
        "{%0,%1,%2,%3}, {%4,%5,%6,%7}, {%8,%9}, {%0,%1,%2,%3};"              \
        : "+f"(acc[0]), "+f"(acc[1]), "+f"(acc[2]), "+f"(acc[3])             \
        : "r"(a0), "r"(a1), "r"(a2), "r"(a3), "r"(b0), "r"(b1))

// ---------------- projection GEMM (tf32 mma.sync, 128x128 CTA tile, R13 winner) ----------------
#define GBM 128
#define GBN 128
#define GBK 32
#define ASTR 136
#define BSTR 136

__global__ __launch_bounds__(256) void gemm5_tc(
    const float* __restrict__ hs, const float* __restrict__ ce,
    const float* __restrict__ Wq,  const float* __restrict__ bq,
    const float* __restrict__ Wk,  const float* __restrict__ bk,
    const float* __restrict__ Wv,  const float* __restrict__ bv,
    const float* __restrict__ Wcq, const float* __restrict__ bcq,
    const float* __restrict__ Wck, const float* __restrict__ bck)
{
    const int which = blockIdx.z;
    const float* A;
    const float* Wt;
    const float* bias;
    float scale = 1.0f;
    float* C;
    switch (which) {
        case 0: A = hs; Wt = Wq;  bias = bq;  C = g_q;  break;
        case 1: A = hs; Wt = Wk;  bias = bk;  C = g_k;  break;
        case 2: A = hs; Wt = Wv;  bias = bv;  C = g_v;  break;
        case 3: A = ce; Wt = Wcq; bias = bcq; C = g_cq; scale = SCALE; break;
        default:A = ce; Wt = Wck; bias = bck; C = g_ck; break;
    }

    __shared__ uint32_t sA[GBK][ASTR];
    __shared__ uint32_t sB[GBK][BSTR];

    const int tid  = threadIdx.x;
    const int warp = tid >> 5;
    const int lane = tid & 31;
    const int wm   = warp & 3;
    const int wn   = warp >> 2;
    const int g    = lane >> 2;
    const int t4   = lane & 3;
    const int m0   = blockIdx.y * GBM;
    const int n0   = blockIdx.x * GBN;

    const int am = tid & 127;
    const int ak = (tid >> 7) * 16;
    const int bk2 = tid >> 3;
    const int bn2 = (tid & 7) * 4;

    const float* Abase = A  + (size_t)(m0 + am) * E + ak;
    const float* Bbase = Wt + (size_t)bk2 * E + n0 + bn2;

    float acc[2][8][4];
    #pragma unroll
    for (int mt = 0; mt < 2; mt++)
        #pragma unroll
        for (int nt = 0; nt < 8; nt++)
            #pragma unroll
            for (int x = 0; x < 4; x++) acc[mt][nt][x] = 0.f;

    for (int k0 = 0; k0 < E; k0 += GBK) {
        #pragma unroll
        for (int i = 0; i < 4; i++) {
            float4 v = *(const float4*)(Abase + k0 + i * 4);
            sA[ak + i*4 + 0][am] = f2tf32(v.x);
            sA[ak + i*4 + 1][am] = f2tf32(v.y);
            sA[ak + i*4 + 2][am] = f2tf32(v.z);
            sA[ak + i*4 + 3][am] = f2tf32(v.w);
        }
        #pragma unroll
        for (int j = 0; j < 4; j++) {
            float4 v = *(const float4*)(Bbase + (size_t)k0 * E + j * 32);
            uint4 u;
            u.x = f2tf32(v.x); u.y = f2tf32(v.y);
            u.z = f2tf32(v.z); u.w = f2tf32(v.w);
            *(uint4*)&sB[bk2][bn2 + j * 32] = u;
        }
        __syncthreads();

        #pragma unroll
        for (int ks = 0; ks < 4; ks++) {
            const int kk = ks * 8;
            uint32_t af[2][4];
            #pragma unroll
            for (int mt = 0; mt < 2; mt++) {
                int mb = wm * 32 + mt * 16 + g;
                af[mt][0] = sA[kk + t4    ][mb];
                af[mt][1] = sA[kk + t4    ][mb + 8];
                af[mt][2] = sA[kk + t4 + 4][mb];
                af[mt][3] = sA[kk + t4 + 4][mb + 8];
            }
            uint32_t bf[8][2];
            #pragma unroll
            for (int nt = 0; nt < 8; nt++) {
                int nb = wn * 64 + nt * 8 + g;
                bf[nt][0] = sB[kk + t4    ][nb];
                bf[nt][1] = sB[kk + t4 + 4][nb];
            }
            #pragma unroll
            for (int mt = 0; mt < 2; mt++)
                #pragma unroll
                for (int nt = 0; nt < 8; nt++)
                    MMA_TF32(acc[mt][nt],
                             af[mt][0], af[mt][1], af[mt][2], af[mt][3],
                             bf[nt][0], bf[nt][1]);
        }
        __syncthreads();
    }

    #pragma unroll
    for (int nt = 0; nt < 8; nt++) {
        int col = n0 + wn * 64 + nt * 8 + 2 * t4;
        float b0v = bias[col], b1v = bias[col + 1];
        #pragma unroll
        for (int mt = 0; mt < 2; mt++) {
            int row = m0 + wm * 32 + mt * 16 + g;
            float2 o;
            o.x = (acc[mt][nt][0] + b0v) * scale;
            o.y = (acc[mt][nt][1] + b1v) * scale;
            *(float2*)&C[(size_t)row * E + col] = o;
            o.x = (acc[mt][nt][2] + b0v) * scale;
            o.y = (acc[mt][nt][3] + b1v) * scale;
            *(float2*)&C[(size_t)(row + 8) * E + col] = o;
        }
    }
}

// ---------------- lam ----------------
__global__ __launch_bounds__(256) void lam_kernel(
    const float* __restrict__ Wlqc, const float* __restrict__ blqc,
    const float* __restrict__ Wlqq, const float* __restrict__ blqq,
    const float* __restrict__ Wlkc, const float* __restrict__ blkc,
    const float* __restrict__ Wlkk, const float* __restrict__ blkk)
{
    int gw   = (blockIdx.x * blockDim.x + threadIdx.x) >> 5;
    int lane = threadIdx.x & 31;
    if (gw >= S * Hh) return;
    int s = gw / Hh, h = gw % Hh;
    size_t base = (size_t)s * E + h * D;

    float a = g_cq[base + lane] * Wlqc[lane] + g_cq[base + lane + 32] * Wlqc[lane + 32]
            + g_q [base + lane] * Wlqq[lane] + g_q [base + lane + 32] * Wlqq[lane + 32];
    float b = g_ck[base + lane] * Wlkc[lane] + g_ck[base + lane + 32] * Wlkc[lane + 32]
            + g_k [base + lane] * Wlkk[lane] + g_k [base + lane + 32] * Wlkk[lane + 32];
    #pragma unroll
    for (int o = 16; o; o >>= 1) {
        a += __shfl_xor_sync(0xffffffffu, a, o);
        b += __shfl_xor_sync(0xffffffffu, b, o);
    }
    if (lane == 0) {
        float lq = 1.f / (1.f + __expf(-(a + blqc[0] + blqq[0])));
        float lk = 1.f / (1.f + __expf(-(b + blkc[0] + blkk[0])));
        g_lam[gw] = 1.f - lq - lk;
    }
}

// ---------------- attn kernel (STREAMING, runs FIRST): npout[t] = exp(score); g_rsum = row sums ----
// TQ=32, 256 threads, thread = 2 rows x 4 cols. No band registers.
// No max-subtraction: scores O(10) or <= -1e4 (exp underflows to exact 0) -> no overflow.
#define KSTR 64

__global__ __launch_bounds__(256) void attn_kernel(
    const int* __restrict__ amask, float* __restrict__ npout)
{
    __shared__ float sQT[64 * TQ];     // [d][r] q^T (pre-scaled)
    __shared__ float sKT[64 * KSTR];   // [d][c] k^T
    __shared__ float sFm[64];

    const int h   = blockIdx.y;
    const int q0  = blockIdx.x * TQ;
    const int tid = threadIdx.x;
    const int rg  = tid >> 4;
    const int cg  = tid & 15;
    const int r0  = rg << 1;
    const int c0  = cg << 2;

    {
        int lr = tid >> 3;
        int d0 = (tid & 7) << 3;
        const float4* qp = (const float4*)(g_q + (size_t)(q0 + lr) * E + h * D + d0);
        float4 q1 = qp[0], q2 = qp[1];
        sQT[(d0+0)*TQ + lr] = q1.x * SCALE; sQT[(d0+1)*TQ + lr] = q1.y * SCALE;
        sQT[(d0+2)*TQ + lr] = q1.z * SCALE; sQT[(d0+3)*TQ + lr] = q1.w * SCALE;
        sQT[(d0+4)*TQ + lr] = q2.x * SCALE; sQT[(d0+5)*TQ + lr] = q2.y * SCALE;
        sQT[(d0+6)*TQ + lr] = q2.z * SCALE; sQT[(d0+7)*TQ + lr] = q2.w * SCALE;
    }

    float* nprow0 = npout + ((size_t)(q0 + r0 + 0) * Hh + h) * TT;
    float* nprow1 = npout + ((size_t)(q0 + r0 + 1) * Hh + h) * TT;
    float sum0 = 0.f, sum1 = 0.f;

    const int lc  = tid >> 2;
    const int ld0 = (tid & 3) << 4;

    for (int b = 0; b < NKB; b++) {
        const int kb0 = q0 - Wb + b * 64;
        __syncthreads();
        {
            int j = kb0 + lc;
            bool ok = (j >= 0) && (j < S);
            const float4* kp = (const float4*)(g_k + (size_t)(ok ? j : 0) * E + h * D + ld0);
            #pragma unroll
            for (int u4 = 0; u4 < 4; u4++) {
                float4 kv = ok ? kp[u4] : make_float4(0.f,0.f,0.f,0.f);
                int dd = ld0 + u4 * 4;
                sKT[(dd+0)*KSTR + lc] = kv.x; sKT[(dd+1)*KSTR + lc] = kv.y;
                sKT[(dd+2)*KSTR + lc] = kv.z; sKT[(dd+3)*KSTR + lc] = kv.w;
            }
            if (tid < 64) {
                int jj = kb0 + tid;
                sFm[tid] = (jj >= 0 && jj < S && amask[jj] != 0) ? -10000.f : 0.f;
            }
        }
        __syncthreads();

        float acc[2][4] = {{0.f,0.f,0.f,0.f},{0.f,0.f,0.f,0.f}};
        #pragma unroll 8
        for (int kk = 0; kk < 64; kk++) {
            float2 qv = *(const float2*)&sQT[kk*TQ  + r0];
            float4 kv = *(const float4*)&sKT[kk*KSTR + c0];
            acc[0][0] += qv.x*kv.x; acc[0][1] += qv.x*kv.y;
            acc[0][2] += qv.x*kv.z; acc[0][3] += qv.x*kv.w;
            acc[1][0] += qv.y*kv.x; acc[1][1] += qv.y*kv.y;
            acc[1][2] += qv.y*kv.z; acc[1][3] += qv.y*kv.w;
        }

        #pragma unroll
        for (int jx = 0; jx < 4; jx++) {
            int c = c0 + jx;
            int j = kb0 + c;
            bool okj = (j >= 0) && (j < S);
            float fm = sFm[c];
            {
                int t = b * 64 + c - (r0 + 0);
                if (t >= 0 && t <= 512 && okj) {
                    float e = __expf(acc[0][jx] + fm);
                    nprow0[t] = e;
                    sum0 += e;
                }
            }
            {
                int t = b * 64 + c - (r0 + 1);
                if (t >= 0 && t <= 512 && okj) {
                    float e = __expf(acc[1][jx] + fm);
                    nprow1[t] = e;
                    sum1 += e;
                }
            }
        }
    }

    // reduce row sums over the 16 col-threads (cg in low 4 bits of lane)
    #pragma unroll
    for (int o = 8; o; o >>= 1) {
        sum0 += __shfl_xor_sync(0xffffffffu, sum0, o);
        sum1 += __shfl_xor_sync(0xffffffffu, sum1, o);
    }
    if (cg == 0) {
        g_rsum[(q0 + r0 + 0) * Hh + h] = sum0;
        g_rsum[(q0 + r0 + 1) * Hh + h] = sum1;
    }
}

// ---------------- quasi kernel (runs SECOND; combines): np = exp*inv + lam*sigmoid(quasi) ----------------
__global__ __launch_bounds__(256) void quasi_kernel(
    const int* __restrict__ amask, float* __restrict__ npout)
{
    __shared__ float sCQT[64 * TQQ];   // [d][r] cq rows
    __shared__ float sCKT[64 * KSTR];  // [d][c] cq key block
    __shared__ float sFm[64];

    const int h   = blockIdx.y;
    const int q0  = blockIdx.x * TQQ;
    const int tid = threadIdx.x;
    const int rg  = tid >> 4;          // 0..15 -> rows 4rg..4rg+3
    const int cg  = tid & 15;
    const int r0  = rg << 2;
    const int c0  = cg << 2;

    {
        int lr = tid >> 2;             // 0..63
        int d0 = (tid & 3) << 4;       // 0,16,32,48
        const float4* cqp = (const float4*)(g_cq + (size_t)(q0 + lr) * E + h * D + d0);
        #pragma unroll
        for (int u4 = 0; u4 < 4; u4++) {
            float4 cv = cqp[u4];
            int dd = d0 + u4 * 4;
            sCQT[(dd+0)*TQQ + lr] = cv.x; sCQT[(dd+1)*TQQ + lr] = cv.y;
            sCQT[(dd+2)*TQQ + lr] = cv.z; sCQT[(dd+3)*TQQ + lr] = cv.w;
        }
    }

    float lam[4], inv[4];
    bool  qm[4];
    float* nprow[4];
    #pragma unroll
    for (int i = 0; i < 4; i++) {
        int ig = q0 + r0 + i;
        lam[i] = g_lam[ig * Hh + h];
        inv[i] = 1.f / g_rsum[ig * Hh + h];
        qm[i]  = (amask[ig] != 0);
        nprow[i] = npout + ((size_t)ig * Hh + h) * TT;
    }

    const int lc  = tid >> 2;          // 0..63
    const int ld0 = (tid & 3) << 4;    // 0,16,32,48

    for (int b = 0; b < NKBQ; b++) {
        const int kb0 = q0 - Wb + b * 64;
        __syncthreads();
        {
            int j = kb0 + lc;
            bool ok = (j >= 0) && (j < S);
            const float4* cp = (const float4*)(g_cq + (size_t)(ok ? j : 0) * E + h * D + ld0);
            #pragma unroll
            for (int u4 = 0; u4 < 4; u4++) {
                float4 cv = ok ? cp[u4] : make_float4(0.f,0.f,0.f,0.f);
                int dd = ld0 + u4 * 4;
                sCKT[(dd+0)*KSTR + lc] = cv.x; sCKT[(dd+1)*KSTR + lc] = cv.y;
                sCKT[(dd+2)*KSTR + lc] = cv.z; sCKT[(dd+3)*KSTR + lc] = cv.w;
            }
            if (tid < 64) {
                int jj = kb0 + tid;
                sFm[tid] = (jj >= 0 && jj < S && amask[jj] != 0) ? -10000.f : 0.f;
            }
        }
        __syncthreads();

        float acq[4][4];
        #pragma unroll
        for (int i = 0; i < 4; i++)
            #pragma unroll
            for (int jx = 0; jx < 4; jx++) acq[i][jx] = 0.f;

        #pragma unroll 8
        for (int kk = 0; kk < 64; kk++) {
            float4 qv = *(const float4*)&sCQT[kk*TQQ + r0];
            float4 kv = *(const float4*)&sCKT[kk*KSTR + c0];
            acq[0][0] += qv.x*kv.x; acq[0][1] += qv.x*kv.y; acq[0][2] += qv.x*kv.z; acq[0][3] += qv.x*kv.w;
            acq[1][0] += qv.y*kv.x; acq[1][1] += qv.y*kv.y; acq[1][2] += qv.y*kv.z; acq[1][3] += qv.y*kv.w;
            acq[2][0] += qv.z*kv.x; acq[2][1] += qv.z*kv.y; acq[2][2] += qv.z*kv.z; acq[2][3] += qv.z*kv.w;
            acq[3][0] += qv.w*kv.x; acq[3][1] += qv.w*kv.y; acq[3][2] += qv.w*kv.z; acq[3][3] += qv.w*kv.w;
        }

        #pragma unroll
        for (int jx = 0; jx < 4; jx++) {
            int c = c0 + jx;
            int j = kb0 + c;
            bool okj = (j >= 0) && (j < S);
            float fm = sFm[c];
            #pragma unroll
            for (int i = 0; i < 4; i++) {
                int t = b * 64 + c - (r0 + i);
                if (t >= 0 && t <= 512) {
                    float np = 0.f;
                    if (okj && !qm[i]) {
                        float e = nprow[i][t];   // exp from attn
                        float sg = lam[i] / (1.f + __expf(-(acq[i][jx] + fm)));
                        np = e * inv[i] + sg;
                    }
                    nprow[i][t] = np;
                }
            }
        }
    }
}

// ---------------- PV (SIMT, R7/R13 winner): out = band_pv(new_probs, v) ----------------
#define PSTR 68
#define VSTR 68

__global__ __launch_bounds__(256) void pv_kernel(
    float* __restrict__ outp, const float* __restrict__ npout)
{
    __shared__ float sP[TQP * PSTR];   // [64][68]
    __shared__ float sV[64 * VSTR];    // [64][68]

    const int h   = blockIdx.y;
    const int q0  = blockIdx.x * TQP;
    const int tid = threadIdx.x;
    const int rg  = tid >> 4;          // rows 4rg..4rg+3
    const int dg  = tid & 15;          // d = 4dg..4dg+3

    float acc[4][4];
    #pragma unroll
    for (int i = 0; i < 4; i++)
        #pragma unroll
        for (int j = 0; j < 4; j++) acc[i][j] = 0.f;

    for (int b = 0; b < NKB; b++) {
        int kb0 = q0 - Wb + b * 64;
        __syncthreads();
        {
            int lr  = tid >> 2;
            int c0l = (tid & 3) << 4;
            const float* nprow = npout + ((size_t)(q0 + lr) * Hh + h) * TT;
            #pragma unroll
            for (int x4 = 0; x4 < 4; x4++) {
                int t0 = b * 64 + c0l + x4 * 4 - lr;
                float4 pv4;
                pv4.x = (t0+0 >= 0 && t0+0 <= 512) ? nprow[t0+0] : 0.f;
                pv4.y = (t0+1 >= 0 && t0+1 <= 512) ? nprow[t0+1] : 0.f;
                pv4.z = (t0+2 >= 0 && t0+2 <= 512) ? nprow[t0+2] : 0.f;
                pv4.w = (t0+3 >= 0 && t0+3 <= 512) ? nprow[t0+3] : 0.f;
                *(float4*)&sP[lr * PSTR + c0l + x4 * 4] = pv4;
            }
        }
        {
            int c   = tid >> 2;
            int d0l = (tid & 3) << 4;
            int j = kb0 + c;
            bool ok = (j >= 0) && (j < S);
            const float4* vp = (const float4*)(g_v + (size_t)(ok ? j : 0) * E + h * D + d0l);
            #pragma unroll
            for (int u4 = 0; u4 < 4; u4++) {
                float4 x = ok ? vp[u4] : make_float4(0.f,0.f,0.f,0.f);
                *(float4*)&sV[c * VSTR + d0l + u4 * 4] = x;
            }
        }
        __syncthreads();

        #pragma unroll 4
        for (int c = 0; c < 64; c++) {
            float4 vv = *(const float4*)&sV[c * VSTR + 4 * dg];
            float p0 = sP[(4*rg+0) * PSTR + c];
            float p1 = sP[(4*rg+1) * PSTR + c];
            float p2 = sP[(4*rg+2) * PSTR + c];
            float p3 = sP[(4*rg+3) * PSTR + c];
            acc[0][0] += p0*vv.x; acc[0][1] += p0*vv.y; acc[0][2] += p0*vv.z; acc[0][3] += p0*vv.w;
            acc[1][0] += p1*vv.x; acc[1][1] += p1*vv.y; acc[1][2] += p1*vv.z; acc[1][3] += p1*vv.w;
            acc[2][0] += p2*vv.x; acc[2][1] += p2*vv.y; acc[2][2] += p2*vv.z; acc[2][3] += p2*vv.w;
            acc[3][0] += p3*vv.x; acc[3][1] += p3*vv.y; acc[3][2] += p3*vv.z; acc[3][3] += p3*vv.w;
        }
    }

    #pragma unroll
    for (int i = 0; i < 4; i++) {
        float4 o;
        o.x = acc[i][0]; o.y = acc[i][1]; o.z = acc[i][2]; o.w = acc[i][3];
        *(float4*)(outp + (size_t)(q0 + 4*rg + i) * E + h * D + 4 * dg) = o;
    }
}

// ---------------- launch ----------------
extern "C" void kernel_launch(void* const* d_in, const int* in_sizes, int n_in,
                              void* d_out, int out_size)
{
    (void)in_sizes; (void)n_in; (void)out_size;

    const float* hs    = (const float*)d_in[0];
    const float* ce    = (const float*)d_in[1];
    const int*   amask = (const int*)  d_in[2];
    // d_in[3] is is_index_masked == (attention_mask != 0); derived from amask.
    const float* Wq   = (const float*)d_in[4];
    const float* bq   = (const float*)d_in[5];
    const float* Wk   = (const float*)d_in[6];
    const float* bk   = (const float*)d_in[7];
    const float* Wv   = (const float*)d_in[8];
    const float* bv   = (const float*)d_in[9];
    const float* Wcq  = (const float*)d_in[10];
    const float* bcq  = (const float*)d_in[11];
    const float* Wck  = (const float*)d_in[12];
    const float* bck  = (const float*)d_in[13];
    const float* Wlqc = (const float*)d_in[14];
    const float* blqc = (const float*)d_in[15];
    const float* Wlqq = (const float*)d_in[16];
    const float* blqq = (const float*)d_in[17];
    const float* Wlkc = (const float*)d_in[18];
    const float* blkc = (const float*)d_in[19];
    const float* Wlkk = (const float*)d_in[20];
    const float* blkk = (const float*)d_in[21];

    float* outp  = (float*)d_out;
    float* npout = outp + (size_t)S * E;   // tuple output: [out | new_probs]

    dim3 gg(E / GBN, S / GBM, 5);
    gemm5_tc<<<gg, 256>>>(hs, ce, Wq, bq, Wk, bk, Wv, bv, Wcq, bcq, Wck, bck);

    lam_kernel<<<(S * Hh) / 8, 256>>>(Wlqc, blqc, Wlqq, blqq, Wlkc, blkc, Wlkk, blkk);

    attn_kernel<<<dim3(S / TQ, Hh), 256>>>(amask, npout);

    quasi_kernel<<<dim3(S / TQQ, Hh), 256>>>(amask, npout);

    pv_kernel<<<dim3(S / TQP, Hh), 256>>>(outp, npout);
}